// round 17
// baseline (speedup 1.0000x reference)
#include <cuda_runtime.h>
#include <cuda_bf16.h>
#include <cstdint>

#define TT 8192
#define DD 64
#define MM 4

// ---------------- scratch (device globals; no allocation) ----------------
__device__ float g_Q [TT * DD];            // Q row-major [t][d]           2MB
__device__ float g_K [MM * TT * DD];       // K row-major [m][t][d]        8MB
__device__ float g_V2[MM * TT * 2];        // V interleaved [m][t][e]      256KB
__device__ float g_T2[MM * TT];            // t2 per modality (t1 = m=0)
__device__ int   g_idx[MM * TT];           // searchsorted results
__device__ float g_S [MM * TT * 128];      // prefix sums [m][t][d*2+e]    16MB
__device__ uint4 g_WF[15 * 1024];          // W fragments [u*3+l][(ks*8+nt)*32+lane]
__device__ float g_pre2[MM * 128 * 128];   // per-64-t-block totals [m][blk][d*2+e]

// ---------------- bf16 split helpers ----------------
__device__ __forceinline__ uint32_t pk(unsigned short a, unsigned short b) {
    return (uint32_t)a | ((uint32_t)b << 16);
}
__device__ __forceinline__ void split2(float fx, float fy, uint32_t& h, uint32_t& l) {
    __nv_bfloat16 h0 = __float2bfloat16(fx), h1 = __float2bfloat16(fy);
    h = pk(__bfloat16_as_ushort(h0), __bfloat16_as_ushort(h1));
    l = pk(__bfloat16_as_ushort(__float2bfloat16(fx - __bfloat162float(h0))),
           __bfloat16_as_ushort(__float2bfloat16(fy - __bfloat162float(h1))));
}
__device__ __forceinline__ void mma_bf16(float* d, uint32_t a0, uint32_t a1,
                                         uint32_t a2, uint32_t a3,
                                         uint32_t b0, uint32_t b1) {
    asm volatile(
        "mma.sync.aligned.m16n8k16.row.col.f32.bf16.bf16.f32 "
        "{%0,%1,%2,%3},{%4,%5,%6,%7},{%8,%9},{%0,%1,%2,%3};"
        : "+f"(d[0]), "+f"(d[1]), "+f"(d[2]), "+f"(d[3])
        : "r"(a0), "r"(a1), "r"(a2), "r"(a3), "r"(b0), "r"(b1));
}

#define MLP_SMEM (4608 * 4)   // output staging only (18.4KB)

// ---------------- Kernel 0: precompute W fragments -----------------------
__global__ void __launch_bounds__(256) k_wprep(
    const float* __restrict__ wq_w, const float* __restrict__ wk_w)
{
    const int ul = blockIdx.x;          // 0..14
    const int u = ul / 3, l = ul % 3;
    const float* W = (u == 0) ? wq_w : wk_w + (size_t)(u - 1) * 3 * DD * DD;
    const float* Wlay = W + (size_t)l * DD * DD;

    const int tid = threadIdx.x;
    const int w = tid >> 5, lane = tid & 31;
    const int g = lane >> 2, q = lane & 3;
    const int n = w * 8 + g;

    #pragma unroll
    for (int ks = 0; ks < 4; ks++) {
        const float* wp = Wlay + (ks * 16 + 2 * q) * 64 + n;
        float b00 = wp[0],      b01 = wp[64];
        float b10 = wp[8 * 64], b11 = wp[9 * 64];
        uint4 v;
        split2(b00, b01, v.x, v.z);
        split2(b10, b11, v.y, v.w);
        g_WF[ul * 1024 + (ks * 8 + w) * 32 + lane] = v;
    }
}

// ---------------- Kernel 1: 5 MLPs, 64-row tiles, register-resident A -----
// grid (T/64, 5), 128 threads (4 warps); warp w owns rows w*16 .. w*16+15.
__global__ void __launch_bounds__(128, 4) k_mlp(
    const float* __restrict__ X,
    const float* __restrict__ wq_b, const float* __restrict__ wk_b)
{
    extern __shared__ __align__(16) float St[];   // staging [4608]

    const int tid  = threadIdx.x;
    const int w    = tid >> 5;
    const int lane = tid & 31;
    const int g    = lane >> 2;   // 0..7
    const int q    = lane & 3;    // 0..3
    const int u    = blockIdx.y;
    const int base = blockIdx.x * 64;
    const int m_in = (u == 0) ? 0 : (u - 1);
    const float* B = (u == 0) ? wq_b : wk_b + (size_t)(u - 1) * 3 * DD;

    uint4 AH[4], AL[4];
    {
        const int r0 = base + w * 16 + g;
        const float* x0 = X + ((size_t)m_in * TT + r0) * DD;
        const float* x1 = x0 + 8 * DD;
        #pragma unroll
        for (int ks = 0; ks < 4; ks++) {
            float2 a0 = *(const float2*)(x0 + ks * 16 + 2 * q);
            float2 a2 = *(const float2*)(x0 + ks * 16 + 8 + 2 * q);
            float2 a1 = *(const float2*)(x1 + ks * 16 + 2 * q);
            float2 a3 = *(const float2*)(x1 + ks * 16 + 8 + 2 * q);
            if (u >= 1) {
                if (ks == 0 && q == 0) {
                    ((float2*)g_V2)[(size_t)m_in * TT + r0]     = a0;
                    ((float2*)g_V2)[(size_t)m_in * TT + r0 + 8] = a1;
                }
                if (ks == 3 && q == 3) {
                    g_T2[(size_t)m_in * TT + r0]     = a2.y;
                    g_T2[(size_t)m_in * TT + r0 + 8] = a3.y;
                }
            }
            split2(a0.x, a0.y, AH[ks].x, AL[ks].x);
            split2(a2.x, a2.y, AH[ks].y, AL[ks].y);
            split2(a1.x, a1.y, AH[ks].z, AL[ks].z);
            split2(a3.x, a3.y, AH[ks].w, AL[ks].w);
        }
    }

    #pragma unroll
    for (int l = 0; l < 3; l++) {
        const uint4* wf = g_WF + (u * 3 + l) * 1024;

        float d[8][4];
        #pragma unroll
        for (int nt = 0; nt < 8; nt++)
            #pragma unroll
            for (int j = 0; j < 4; j++) d[nt][j] = 0.0f;

        #pragma unroll
        for (int ks = 0; ks < 4; ks++) {
            #pragma unroll
            for (int nt = 0; nt < 8; nt++) {
                const uint4 b = __ldg(wf + (ks * 8 + nt) * 32 + lane);
                mma_bf16(d[nt], AH[ks].x, AH[ks].z, AH[ks].y, AH[ks].w, b.x, b.y);
                mma_bf16(d[nt], AH[ks].x, AH[ks].z, AH[ks].y, AH[ks].w, b.z, b.w);
                mma_bf16(d[nt], AL[ks].x, AL[ks].z, AL[ks].y, AL[ks].w, b.x, b.y);
            }
        }

        if (l < 2) {
            #pragma unroll
            for (int ksn = 0; ksn < 4; ksn++) {
                const int nt0 = 2 * ksn, nt1 = nt0 + 1;
                const int c0 = nt0 * 8 + 2 * q, c1 = nt1 * 8 + 2 * q;
                float2 b0 = __ldg((const float2*)(B + l * 64 + c0));
                float2 b1 = __ldg((const float2*)(B + l * 64 + c1));
                float f0x = fmaxf(d[nt0][0] + b0.x, 0.0f);
                float f0y = fmaxf(d[nt0][1] + b0.y, 0.0f);
                float f1x = fmaxf(d[nt1][0] + b1.x, 0.0f);
                float f1y = fmaxf(d[nt1][1] + b1.y, 0.0f);
                float f2x = fmaxf(d[nt0][2] + b0.x, 0.0f);
                float f2y = fmaxf(d[nt0][3] + b0.y, 0.0f);
                float f3x = fmaxf(d[nt1][2] + b1.x, 0.0f);
                float f3y = fmaxf(d[nt1][3] + b1.y, 0.0f);
                split2(f0x, f0y, AH[ksn].x, AL[ksn].x);
                split2(f1x, f1y, AH[ksn].y, AL[ksn].y);
                split2(f2x, f2y, AH[ksn].z, AL[ksn].z);
                split2(f3x, f3y, AH[ksn].w, AL[ksn].w);
            }
        } else {
            // final layer: row-major staging for BOTH Q and K
            const int row0 = w * 16 + g;   // 0..63
            #pragma unroll
            for (int nt = 0; nt < 8; nt++) {
                const int col = nt * 8 + 2 * q;
                float2 bb = __ldg((const float2*)(B + 128 + col));
                St[row0 * 72 + col]           = d[nt][0] + bb.x;
                St[row0 * 72 + col + 1]       = d[nt][1] + bb.y;
                St[(row0 + 8) * 72 + col]     = d[nt][2] + bb.x;
                St[(row0 + 8) * 72 + col + 1] = d[nt][3] + bb.y;
            }
            __syncthreads();
            const int row = tid >> 1, c0 = (tid & 1) * 32;
            float* dst = (u == 0) ? g_Q + (size_t)(base + row) * 64
                                  : g_K + ((size_t)m_in * TT + base + row) * 64;
            #pragma unroll
            for (int qq = 0; qq < 8; qq++) {
                float4 v = *(float4*)&St[row * 72 + c0 + qq * 4];
                *(float4*)&dst[c0 + qq * 4] = v;
            }
            if (u >= 1) {
                // per-block K.V totals for the scan's carry bases
                const int dd = tid >> 1, e = tid & 1;
                const float* vv = g_V2 + ((size_t)m_in * TT + base) * 2 + e;
                float s = 0.0f;
                #pragma unroll
                for (int r = 0; r < 64; r++)
                    s += St[r * 72 + dd] * __ldg(vv + r * 2);
                g_pre2[((size_t)m_in * 128 + blockIdx.x) * 128 + tid] = s;
            }
        }
    }
}

// ---------------- Kernel 2: serial-carry scan (S in [m][t][d*2+e]) + idx --
// blocks 0..255: scan; block = (m, 128-t chunk). 256 threads = (d,e,half).
// blocks 256..383: searchsorted + zero output.
__global__ void __launch_bounds__(256) k_scanIdx(float* __restrict__ out)
{
    const int tid = threadIdx.x;

    if (blockIdx.x >= 256) {
        const int gid = (blockIdx.x - 256) * 256 + tid;   // [0, MM*TT)
        if (gid < TT)
            ((float2*)out)[gid] = make_float2(0.0f, 0.0f);
        const int t = gid & (TT - 1);
        const int m = gid >> 13;
        const float key = g_T2[t];
        const float* arr = g_T2 + (size_t)m * TT;
        int lo = 0, hi = TT;
        while (lo < hi) {
            int mid = (lo + hi) >> 1;
            if (arr[mid] <= key) lo = mid + 1; else hi = mid;
        }
        g_idx[gid] = lo - 1;
        return;
    }

    __shared__ float tile[2][32][128];

    const int m  = blockIdx.x >> 6;
    const int c  = blockIdx.x & 63;      // 128-t chunk
    const int de = tid & 127;
    const int h  = tid >> 7;
    const int d  = de >> 1, e = de & 1;

    // carry base: sum of preceding 64-t block totals
    float acc = 0.0f;
    {
        const float* pp = g_pre2 + (size_t)m * 128 * 128 + de;
        const int nb = 2 * c + h;
        for (int b = 0; b < nb; b++) acc += __ldg(pp + (size_t)b * 128);
    }

    const int tbase = c * 128 + h * 64;
    const float* kp = g_K + ((size_t)m * TT + tbase) * 64 + d;
    const float* vp = g_V2 + ((size_t)m * TT + tbase) * 2 + e;

    #pragma unroll
    for (int sc = 0; sc < 2; sc++) {
        #pragma unroll
        for (int j = 0; j < 32; j++) {
            const int tt = sc * 32 + j;
            acc += __ldg(kp + (size_t)tt * 64) * __ldg(vp + (size_t)tt * 2);
            tile[h][j][de] = acc;
        }
        __syncthreads();
        #pragma unroll
        for (int i = 0; i < 8; i++) {
            const int f  = i * 256 + tid;
            const int hh = f >> 10, j = (f >> 5) & 31, c4 = f & 31;
            const int t  = c * 128 + hh * 64 + sc * 32 + j;
            float4 v = *(float4*)&tile[hh][j][c4 * 4];
            *(float4*)&g_S[((size_t)m * TT + t) * 128 + c4 * 4] = v;
        }
        __syncthreads();
    }
}

// ---------------- Kernel 3: coalesced gather + contract + atomics ---------
// grid (T/64, M*2): blockIdx.y = m*2 + dhalf. Thread (lt, dq) reads 64B
// contiguous from the (m, idx) S-row.
__global__ void __launch_bounds__(256) k_gath(float* __restrict__ out)
{
    __shared__ float Qs[64 * 33];
    __shared__ float2 red[256];

    const int m   = blockIdx.y >> 1;
    const int dh  = blockIdx.y & 1;
    const int t0  = blockIdx.x * 64;
    const int tid = threadIdx.x;
    const int lt  = tid & 63;
    const int dq  = tid >> 6;

    {
        const int r = tid >> 2, c4 = tid & 3;
        const float* src = g_Q + (size_t)(t0 + r) * 64 + dh * 32 + c4 * 8;
        #pragma unroll
        for (int j = 0; j < 2; j++) {
            float4 v = ((const float4*)src)[j];
            const int c = c4 * 8 + j * 4;
            Qs[r * 33 + c + 0] = v.x;
            Qs[r * 33 + c + 1] = v.y;
            Qs[r * 33 + c + 2] = v.z;
            Qs[r * 33 + c + 3] = v.w;
        }
    }

    const int idx = g_idx[(size_t)m * TT + t0 + lt];
    __syncthreads();

    float a0 = 0.0f, a1 = 0.0f;
    if (idx >= 0) {
        // S row: 128 floats; this thread covers d = dh*32+dq*8 .. +8 (16 floats)
        const float4* sp = (const float4*)(g_S + ((size_t)m * TT + idx) * 128
                                           + (dh * 32 + dq * 8) * 2);
        #pragma unroll
        for (int j = 0; j < 4; j++) {
            float4 s = __ldg(sp + j);              // (d,e0),(d,e1),(d+1,e0),(d+1,e1)
            const float q0 = Qs[lt * 33 + dq * 8 + j * 2];
            const float q1 = Qs[lt * 33 + dq * 8 + j * 2 + 1];
            a0 += q0 * s.x + q1 * s.z;
            a1 += q0 * s.y + q1 * s.w;
        }
    }
    red[tid] = make_float2(a0, a1);
    __syncthreads();

    if (dq == 0) {
        float ax = 0.0f, ay = 0.0f;
        #pragma unroll
        for (int q = 0; q < 4; q++) {
            float2 v = red[lt + 64 * q];
            ax += v.x; ay += v.y;
        }
        atomicAdd(out + (size_t)(t0 + lt) * 2 + 0, ax);
        atomicAdd(out + (size_t)(t0 + lt) * 2 + 1, ay);
    }
}

// ---------------- launch ----------------
extern "C" void kernel_launch(void* const* d_in, const int* in_sizes, int n_in,
                              void* d_out, int out_size)
{
    const float* X    = (const float*)d_in[0];
    const float* wq_w = (const float*)d_in[1];
    const float* wq_b = (const float*)d_in[2];
    const float* wk_w = (const float*)d_in[3];
    const float* wk_b = (const float*)d_in[4];
    float* out = (float*)d_out;

    k_wprep  <<<15, 256>>>(wq_w, wk_w);
    k_mlp    <<<dim3(TT / 64, 5), 128, MLP_SMEM>>>(X, wq_b, wk_b);
    k_scanIdx<<<256 + 128, 256>>>(out);
    k_gath   <<<dim3(TT / 64, MM * 2), 256>>>(out);
}